// round 13
// baseline (speedup 1.0000x reference)
#include <cuda_runtime.h>
#include <cuda_bf16.h>

// Problem constants
#define NN 4
#define QL 64
#define KL 64
#define DD 768
#define HH 16
#define HD 48
#define EE 300
#define NH (NN*HH)   // 64
#define ESPLIT 5     // e-chunks of 64

typedef unsigned long long ull;

// Packed fp32x2 helpers (SASS FADD2/FFMA2; numerics identical to 2x scalar rn)
#define PK2(d, lo, hi)    asm("mov.b64 %0, {%1, %2};" : "=l"(d) : "f"(lo), "f"(hi))
#define UPK2(lo, hi, s)   asm("mov.b64 {%0, %1}, %2;" : "=f"(lo), "=f"(hi) : "l"(s))
#define FADD2(d, a, b)    asm("add.rn.f32x2 %0, %1, %2;" : "=l"(d) : "l"(a), "l"(b))
#define FFMA2(d, a, b, c) asm("fma.rn.f32x2 %0, %1, %2, %3;" : "=l"(d) : "l"(a), "l"(b), "l"(c))

__device__ __forceinline__ ull relu2(ull p) {
    float x, y; UPK2(x, y, p);
    x = fmaxf(x, 0.f); y = fmaxf(y, 0.f);
    ull r; PK2(r, x, y); return r;
}

// Scratch (device globals — no allocation allowed). 128B-aligned for float4 access.
// Q/K/V hold TWO k-halves (proj k-split); consumers sum halves during staging.
__device__ __align__(128) float g_Q[2*NN*QL*DD];
__device__ __align__(128) float g_K[2*KL*DD];
__device__ __align__(128) float g_V[2*KL*DD];
__device__ __align__(128) float g_A[NH*EE*QL];          // [nh][e][q]
__device__ __align__(128) float g_B[NH*KL*QL];          // [nh][k][q]
__device__ __align__(128) float g_Wp[ESPLIT*NH*KL*QL];  // e-partials of [nh][k][q]

// ---------------------------------------------------------------------------
// Kernel 1: fused Q/K/V projections, k-split in 2 halves.
// grid (6 row-tiles, 24 col-tiles, 2 k-halves).
// ---------------------------------------------------------------------------
__global__ __launch_bounds__(256) void proj_kernel(
    const float* __restrict__ qin, const float* __restrict__ kin,
    const float* __restrict__ vin,
    const float* __restrict__ Wq, const float* __restrict__ Wk,
    const float* __restrict__ Wv,
    const float* __restrict__ bq, const float* __restrict__ bk,
    const float* __restrict__ bv,
    float* __restrict__ Qo, float* __restrict__ Ko, float* __restrict__ Vo)
{
    __shared__ float As[32][64];   // [k][m] transposed (256B rows, float4-safe)
    __shared__ float Bs[32][34];   // [k][c] (136B rows, float2-safe)

    const int rt = blockIdx.x;
    const int c0 = blockIdx.y * 32;
    const int ks = blockIdx.z;          // k half
    const int kbase = ks * (DD / 2);
    const float *X, *Wt, *bias;
    float* Y;
    if (rt < 4)      { X = qin + (size_t)rt * 64 * DD; Wt = Wq; bias = bq;
                       Y = Qo + (size_t)ks * NN * QL * DD + (size_t)rt * 64 * DD; }
    else if (rt == 4){ X = kin; Wt = Wk; bias = bk; Y = Ko + (size_t)ks * KL * DD; }
    else             { X = vin; Wt = Wv; bias = bv; Y = Vo + (size_t)ks * KL * DD; }

    const int tid = threadIdx.x;
    const int tx = tid & 15;       // col group (2 cols)
    const int ty = tid >> 4;       // row group (4 rows)
    const int lr = tid >> 2;       // A load row 0..63
    const int lc = (tid & 3) * 4;  // A load k-offset (and +16)
    const int br = tid >> 3;       // B load k-row 0..31
    const int bc = (tid & 7) * 4;  // B load col

    ull accp[2][2] = {{0ull, 0ull}, {0ull, 0ull}};

    for (int k0 = kbase; k0 < kbase + DD / 2; k0 += 32) {
        const float4 a0 = *(const float4*)(X + (size_t)lr * DD + k0 + lc);
        const float4 a1 = *(const float4*)(X + (size_t)lr * DD + k0 + lc + 16);
        const float4 bb = *(const float4*)(Wt + (size_t)(k0 + br) * DD + c0 + bc);
        As[lc + 0][lr] = a0.x; As[lc + 1][lr] = a0.y;
        As[lc + 2][lr] = a0.z; As[lc + 3][lr] = a0.w;
        As[lc + 16][lr] = a1.x; As[lc + 17][lr] = a1.y;
        As[lc + 18][lr] = a1.z; As[lc + 19][lr] = a1.w;
        Bs[br][bc + 0] = bb.x; Bs[br][bc + 1] = bb.y;
        Bs[br][bc + 2] = bb.z; Bs[br][bc + 3] = bb.w;
        __syncthreads();
#pragma unroll
        for (int kk = 0; kk < 32; kk++) {
            const float4 a = *(const float4*)&As[kk][ty * 4];
            const float2 b = *(const float2*)&Bs[kk][tx * 2];
            const ull a01 = ((const ull*)&a)[0];
            const ull a23 = ((const ull*)&a)[1];
            ull bx2, by2; PK2(bx2, b.x, b.x); PK2(by2, b.y, b.y);
            FFMA2(accp[0][0], a01, bx2, accp[0][0]);
            FFMA2(accp[0][1], a23, bx2, accp[0][1]);
            FFMA2(accp[1][0], a01, by2, accp[1][0]);
            FFMA2(accp[1][1], a23, by2, accp[1][1]);
        }
        __syncthreads();
    }

    const float b0 = (ks == 0) ? bias[c0 + tx * 2]     : 0.f;
    const float b1 = (ks == 0) ? bias[c0 + tx * 2 + 1] : 0.f;
    float c00, c10, c20, c30, c01, c11, c21, c31;
    UPK2(c00, c10, accp[0][0]); UPK2(c20, c30, accp[0][1]);
    UPK2(c01, c11, accp[1][0]); UPK2(c21, c31, accp[1][1]);
    float cj0[4] = {c00, c10, c20, c30};
    float cj1[4] = {c01, c11, c21, c31};
#pragma unroll
    for (int i = 0; i < 4; i++) {
        float2 o = make_float2(cj0[i] + b0, cj1[i] + b1);
        *(float2*)(Y + (size_t)(ty * 4 + i) * DD + c0 + tx * 2) = o;
    }
}

// ---------------------------------------------------------------------------
// Kernel 2: per (n,h) scores. Q and K arrive as 2 k-halves; sum while staging.
// ---------------------------------------------------------------------------
__global__ __launch_bounds__(256) void scores_kernel(
    const float* __restrict__ mem, const float* __restrict__ Q,
    const float* __restrict__ K, float* __restrict__ A, float* __restrict__ B)
{
    const int nh = blockIdx.x;          // 0..63
    const int n = nh >> 4, h = nh & 15;
    const int task = blockIdx.y;        // 0..4 = A e-tiles, 5 = B

    __shared__ float Ls[48][68];        // [d][r] (272B rows, float4-safe)
    __shared__ float Qs[48][68];        // [d][q]

    const int tid = threadIdx.x;
    const int r = tid >> 2;             // 0..63
    const int c = tid & 3;

    {
        const float* srcQ0 = Q + (size_t)(n * QL + r) * DD + h * HD;
        const float* srcQ1 = srcQ0 + (size_t)NN * QL * DD;
#pragma unroll
        for (int j = 0; j < 3; j++) {
            const int d0 = c * 4 + j * 16;
            const float4 q0 = *(const float4*)(srcQ0 + d0);
            const float4 q1 = *(const float4*)(srcQ1 + d0);
            Qs[d0 + 0][r] = q0.x + q1.x; Qs[d0 + 1][r] = q0.y + q1.y;
            Qs[d0 + 2][r] = q0.z + q1.z; Qs[d0 + 3][r] = q0.w + q1.w;
        }
        if (task < 5) {
            const int R = min(64, EE - task * 64);
            const float* srcL = mem + (size_t)(task * 64 + r) * DD + h * HD;
#pragma unroll
            for (int j = 0; j < 3; j++) {
                const int d0 = c * 4 + j * 16;
                float4 vl = make_float4(0.f, 0.f, 0.f, 0.f);
                if (r < R) vl = *(const float4*)(srcL + d0);
                Ls[d0 + 0][r] = vl.x; Ls[d0 + 1][r] = vl.y;
                Ls[d0 + 2][r] = vl.z; Ls[d0 + 3][r] = vl.w;
            }
        } else {
            const float* srcK0 = K + (size_t)r * DD + h * HD;
            const float* srcK1 = srcK0 + (size_t)KL * DD;
#pragma unroll
            for (int j = 0; j < 3; j++) {
                const int d0 = c * 4 + j * 16;
                const float4 k0v = *(const float4*)(srcK0 + d0);
                const float4 k1v = *(const float4*)(srcK1 + d0);
                Ls[d0 + 0][r] = k0v.x + k1v.x; Ls[d0 + 1][r] = k0v.y + k1v.y;
                Ls[d0 + 2][r] = k0v.z + k1v.z; Ls[d0 + 3][r] = k0v.w + k1v.w;
            }
        }
    }
    __syncthreads();

    const int tx = tid & 15, ty = tid >> 4;
    ull accp[4][2];
#pragma unroll
    for (int i = 0; i < 4; i++) { accp[i][0] = 0ull; accp[i][1] = 0ull; }

#pragma unroll 8
    for (int d = 0; d < 48; d++) {
        const float4 a = *(const float4*)&Ls[d][ty * 4];
        const float4 b = *(const float4*)&Qs[d][tx * 4];
        const ull b01 = ((const ull*)&b)[0];
        const ull b23 = ((const ull*)&b)[1];
        ull ax2, ay2, az2, aw2;
        PK2(ax2, a.x, a.x); PK2(ay2, a.y, a.y);
        PK2(az2, a.z, a.z); PK2(aw2, a.w, a.w);
        FFMA2(accp[0][0], b01, ax2, accp[0][0]); FFMA2(accp[0][1], b23, ax2, accp[0][1]);
        FFMA2(accp[1][0], b01, ay2, accp[1][0]); FFMA2(accp[1][1], b23, ay2, accp[1][1]);
        FFMA2(accp[2][0], b01, az2, accp[2][0]); FFMA2(accp[2][1], b23, az2, accp[2][1]);
        FFMA2(accp[3][0], b01, aw2, accp[3][0]); FFMA2(accp[3][1], b23, aw2, accp[3][1]);
    }

    if (task < 5) {
        float* out = A + (size_t)nh * EE * QL;
#pragma unroll
        for (int i = 0; i < 4; i++) {
            int e = task * 64 + ty * 4 + i;
            if (e < EE) {
                float4 o;
                UPK2(o.x, o.y, accp[i][0]); UPK2(o.z, o.w, accp[i][1]);
                *(float4*)(out + (size_t)e * QL + tx * 4) = o;
            }
        }
    } else {
        float* out = B + (size_t)nh * KL * QL;
#pragma unroll
        for (int i = 0; i < 4; i++) {
            float4 o;
            UPK2(o.x, o.y, accp[i][0]); UPK2(o.z, o.w, accp[i][1]);
            *(float4*)(out + (size_t)(ty * 4 + i) * QL + tx * 4) = o;
        }
    }
}

// ---------------------------------------------------------------------------
// Kernel 3 (FUSED tsum+wk, f32x2): one 64-e tile x 16-k strip per block.
//   pass1: Tsh[e][k] = sum_q relu(A[e,q]+B[k,q]) (k local 0..15)
//   pass2: w[k,q] += relu(A[e,q]+B[k,q]) * Tsh[e][k]
// grid (64 nh, 4 k-strips of 16, 5 e-chunks of 64), 256 threads, 1280 blocks.
// ---------------------------------------------------------------------------
__global__ __launch_bounds__(256) void wkfused_kernel(
    const float* __restrict__ A, const float* __restrict__ B,
    float* __restrict__ Wp)
{
    const int nh = blockIdx.x;
    const int kg = blockIdx.y;          // 0..3
    const int es = blockIdx.z;          // 0..4
    const int e0 = es * 64;
    const int ec = min(64, EE - e0);    // 64,64,64,64,44

    __shared__ float Ash[64][64];       // [e][q] (256B rows, float4-safe)
    __shared__ float Bsh[16][66];       // [k-local][q] (264B rows, ull-safe)
    __shared__ float Tsh[64][16];       // [e][k-local] (64B rows)

    const int tid = threadIdx.x;
    const int qx = tid & 15;            // pass2: q4 = qx*4
    const int ky = tid >> 4;            // pass2: local k 0..15
    const int kp = tid & 15;            // pass1: local k
    const int eb = tid >> 4;            // pass1: e group of 4 (0..15)

    const float* Bb = B + ((size_t)nh * KL + kg * 16) * QL;

    // load Bsh (16 x 64): 1 float4/thread
    {
        int k = tid >> 4, qq = (tid & 15) * 4;
        float4 v = *(const float4*)(Bb + (size_t)k * QL + qq);
        Bsh[k][qq + 0] = v.x; Bsh[k][qq + 1] = v.y;
        Bsh[k][qq + 2] = v.z; Bsh[k][qq + 3] = v.w;
    }

    // pass2 per-thread B registers (packed pairs), k = ky
    const float4 b0 = *(const float4*)(Bb + (size_t)ky * QL + qx * 4);
    const ull b0a = ((const ull*)&b0)[0], b0b = ((const ull*)&b0)[1];

    ull w0a = 0ull, w0b = 0ull;

    const float* Ab = A + (size_t)nh * EE * QL;

    // load A tile: 4 float4/thread (zero-pad beyond ec)
#pragma unroll
    for (int i = 0; i < 4; i++) {
        int f = tid + i * 256;
        int e = f >> 4, qq = (f & 15) * 4;
        float4 v = make_float4(0.f, 0.f, 0.f, 0.f);
        if (e < ec) v = *(const float4*)(Ab + (size_t)(e0 + e) * QL + qq);
        *(float4*)&Ash[e][qq] = v;
    }
    __syncthreads();

    // pass1: thread (kp, eb) sums e rows {eb*4 .. eb*4+3} over 64 q (packed pairs)
    {
        ull tacc2[4];
#pragma unroll
        for (int i = 0; i < 4; i++) tacc2[i] = 0ull;
#pragma unroll 8
        for (int q2 = 0; q2 < 32; q2++) {
            const ull b2 = *(const ull*)&Bsh[kp][q2 * 2];
#pragma unroll
            for (int i = 0; i < 4; i++) {
                const ull a2 = *(const ull*)&Ash[eb * 4 + i][q2 * 2];
                ull p; FADD2(p, a2, b2);
                p = relu2(p);
                FADD2(tacc2[i], tacc2[i], p);
            }
        }
#pragma unroll
        for (int i = 0; i < 4; i++) {
            const int e = eb * 4 + i;
            float x, y; UPK2(x, y, tacc2[i]);
            Tsh[e][kp] = (e < ec) ? (x + y) : 0.f;  // zero padded rows
        }
    }
    __syncthreads();

    // pass2: thread (ky, qx) accumulates w[ky][qx*4..+3]
#pragma unroll 8
    for (int e = 0; e < 64; e++) {
        const float4 a = *(const float4*)&Ash[e][qx * 4];
        const ull a01 = ((const ull*)&a)[0];
        const ull a23 = ((const ull*)&a)[1];
        const float t = Tsh[e][ky];
        ull t2; PK2(t2, t, t);
        ull p;
        FADD2(p, a01, b0a); p = relu2(p); FFMA2(w0a, p, t2, w0a);
        FADD2(p, a23, b0b); p = relu2(p); FFMA2(w0b, p, t2, w0b);
    }

    float4 w0;
    UPK2(w0.x, w0.y, w0a); UPK2(w0.z, w0.w, w0b);

    float* Wb = Wp + ((size_t)es * NH + nh) * KL * QL + (size_t)kg * 16 * QL;
    *(float4*)(Wb + (size_t)ky * QL + qx * 4) = w0;
}

// ---------------------------------------------------------------------------
// Kernel 4: out[n,q,h,d] = sum_k (sum_es Wp[es])[nh][k][q] * V[k,h,d]
// grid (64 nh, 4 q-quarters, 3 d-chunks of 16), 256 threads, 1 output each.
// ---------------------------------------------------------------------------
__global__ __launch_bounds__(256) void out_kernel(
    const float* __restrict__ Wp, const float* __restrict__ V, float* __restrict__ out)
{
    const int nh = blockIdx.x;
    const int qy = blockIdx.y;          // q quarter
    const int dz = blockIdx.z;          // d chunk of 16
    const int n = nh >> 4, h = nh & 15;
    const int q0 = qy * 16;
    const int d0 = dz * 16;

    __shared__ float Ws[64][16];   // [k][q-local] (64B rows, float4-safe)
    __shared__ float Vs[64][16];   // [k][d-local] (64B rows, float4-safe)

    const int tid = threadIdx.x;
    const float* Wb = Wp + (size_t)nh * KL * QL + q0;

    // Ws: 1024 floats = 1 float4/thread, summing ESPLIT partials
    {
        int k = tid >> 2, qq = (tid & 3) * 4;
        const float* p = Wb + (size_t)k * QL + qq;
        float4 s = make_float4(0.f, 0.f, 0.f, 0.f);
#pragma unroll
        for (int es = 0; es < ESPLIT; es++) {
            const float4 v = *(const float4*)(p + (size_t)es * NH * KL * QL);
            s.x += v.x; s.y += v.y; s.z += v.z; s.w += v.w;
        }
        *(float4*)&Ws[k][qq] = s;
    }
    // Vs: 1024 floats = 1 float4/thread, summing 2 k-halves
    {
        int k = tid >> 2, d4 = (tid & 3) * 4;
        const float* p0 = V + (size_t)k * DD + h * HD + d0 + d4;
        const float4 v0 = *(const float4*)p0;
        const float4 v1 = *(const float4*)(p0 + (size_t)KL * DD);
        float4 s = make_float4(v0.x + v1.x, v0.y + v1.y, v0.z + v1.z, v0.w + v1.w);
        *(float4*)&Vs[k][d4] = s;
    }
    __syncthreads();

    const int tx = tid & 15;      // d local
    const int ty = tid >> 4;      // q local
    float acc = 0.f;

#pragma unroll 16
    for (int kk = 0; kk < 64; kk++)
        acc = fmaf(Ws[kk][ty], Vs[kk][tx], acc);

    out[(size_t)(n * QL + q0 + ty) * DD + h * HD + d0 + tx] = acc;
}

// ---------------------------------------------------------------------------
// Launch
// Inputs: 0=q 1=k 2=v 3=Wq 4=bq 5=Wk 6=bk 7=Wv 8=bv 9=memory
// ---------------------------------------------------------------------------
extern "C" void kernel_launch(void* const* d_in, const int* in_sizes, int n_in,
                              void* d_out, int out_size)
{
    const float* q   = (const float*)d_in[0];
    const float* k   = (const float*)d_in[1];
    const float* v   = (const float*)d_in[2];
    const float* Wq  = (const float*)d_in[3];
    const float* bq  = (const float*)d_in[4];
    const float* Wk  = (const float*)d_in[5];
    const float* bk  = (const float*)d_in[6];
    const float* Wv  = (const float*)d_in[7];
    const float* bv  = (const float*)d_in[8];
    const float* mem = (const float*)d_in[9];
    float* out = (float*)d_out;

    float *gQ, *gK, *gV, *gA, *gB, *gWp;
    cudaGetSymbolAddress((void**)&gQ, g_Q);
    cudaGetSymbolAddress((void**)&gK, g_K);
    cudaGetSymbolAddress((void**)&gV, g_V);
    cudaGetSymbolAddress((void**)&gA, g_A);
    cudaGetSymbolAddress((void**)&gB, g_B);
    cudaGetSymbolAddress((void**)&gWp, g_Wp);

    // 1. Fused projections, k-split x2 (288 blocks)
    proj_kernel<<<dim3(6, 24, 2), 256>>>(q, k, v, Wq, Wk, Wv, bq, bk, bv, gQ, gK, gV);

    // 2. A (mem·Q) and B (K·Q) scores (consumers sum the k-halves)
    scores_kernel<<<dim3(NH, 6), 256>>>(mem, gQ, gK, gA, gB);

    // 3. Fused T+W partials: 4 k-strips x 5 e-chunks (1280 blocks)
    wkfused_kernel<<<dim3(NH, 4, ESPLIT), 256>>>(gA, gB, gWp);

    // 4. out = (sum of W partials)^T @ V_h (768 blocks, 1 output/thread)
    out_kernel<<<dim3(NH, 4, 3), 256>>>(gWp, gV, out);
}

// round 14
// speedup vs baseline: 1.0354x; 1.0354x over previous
#include <cuda_runtime.h>
#include <cuda_bf16.h>

// Problem constants
#define NN 4
#define QL 64
#define KL 64
#define DD 768
#define HH 16
#define HD 48
#define EE 300
#define NH (NN*HH)   // 64
#define ESPLIT 5     // e-chunks of 64

typedef unsigned long long ull;

// Packed fp32x2 helpers (SASS FADD2/FFMA2; numerics identical to 2x scalar rn)
#define PK2(d, lo, hi)    asm("mov.b64 %0, {%1, %2};" : "=l"(d) : "f"(lo), "f"(hi))
#define UPK2(lo, hi, s)   asm("mov.b64 {%0, %1}, %2;" : "=f"(lo), "=f"(hi) : "l"(s))
#define FADD2(d, a, b)    asm("add.rn.f32x2 %0, %1, %2;" : "=l"(d) : "l"(a), "l"(b))
#define FFMA2(d, a, b, c) asm("fma.rn.f32x2 %0, %1, %2, %3;" : "=l"(d) : "l"(a), "l"(b), "l"(c))

__device__ __forceinline__ ull relu2(ull p) {
    float x, y; UPK2(x, y, p);
    x = fmaxf(x, 0.f); y = fmaxf(y, 0.f);
    ull r; PK2(r, x, y); return r;
}

// Scratch (device globals — no allocation allowed). 128B-aligned for float4 access.
// Q/K/V hold TWO k-halves (proj k-split); consumers sum halves during staging.
__device__ __align__(128) float g_Q[2*NN*QL*DD];
__device__ __align__(128) float g_K[2*KL*DD];
__device__ __align__(128) float g_V[2*KL*DD];
__device__ __align__(128) float g_A[NH*EE*QL];          // [nh][e][q]
__device__ __align__(128) float g_B[NH*KL*QL];          // [nh][k][q]
__device__ __align__(128) float g_Wp[ESPLIT*NH*KL*QL];  // e-partials of [nh][k][q]

// ---------------------------------------------------------------------------
// Kernel 1: fused Q/K/V projections, k-split in 2 halves.
// grid (6 row-tiles, 24 col-tiles, 2 k-halves).
// ---------------------------------------------------------------------------
__global__ __launch_bounds__(256) void proj_kernel(
    const float* __restrict__ qin, const float* __restrict__ kin,
    const float* __restrict__ vin,
    const float* __restrict__ Wq, const float* __restrict__ Wk,
    const float* __restrict__ Wv,
    const float* __restrict__ bq, const float* __restrict__ bk,
    const float* __restrict__ bv,
    float* __restrict__ Qo, float* __restrict__ Ko, float* __restrict__ Vo)
{
    __shared__ float As[32][64];   // [k][m] transposed (256B rows, float4-safe)
    __shared__ float Bs[32][34];   // [k][c] (136B rows, float2-safe)

    const int rt = blockIdx.x;
    const int c0 = blockIdx.y * 32;
    const int ks = blockIdx.z;          // k half
    const int kbase = ks * (DD / 2);
    const float *X, *Wt, *bias;
    float* Y;
    if (rt < 4)      { X = qin + (size_t)rt * 64 * DD; Wt = Wq; bias = bq;
                       Y = Qo + (size_t)ks * NN * QL * DD + (size_t)rt * 64 * DD; }
    else if (rt == 4){ X = kin; Wt = Wk; bias = bk; Y = Ko + (size_t)ks * KL * DD; }
    else             { X = vin; Wt = Wv; bias = bv; Y = Vo + (size_t)ks * KL * DD; }

    const int tid = threadIdx.x;
    const int tx = tid & 15;       // col group (2 cols)
    const int ty = tid >> 4;       // row group (4 rows)
    const int lr = tid >> 2;       // A load row 0..63
    const int lc = (tid & 3) * 4;  // A load k-offset (and +16)
    const int br = tid >> 3;       // B load k-row 0..31
    const int bc = (tid & 7) * 4;  // B load col

    ull accp[2][2] = {{0ull, 0ull}, {0ull, 0ull}};

    for (int k0 = kbase; k0 < kbase + DD / 2; k0 += 32) {
        const float4 a0 = *(const float4*)(X + (size_t)lr * DD + k0 + lc);
        const float4 a1 = *(const float4*)(X + (size_t)lr * DD + k0 + lc + 16);
        const float4 bb = *(const float4*)(Wt + (size_t)(k0 + br) * DD + c0 + bc);
        As[lc + 0][lr] = a0.x; As[lc + 1][lr] = a0.y;
        As[lc + 2][lr] = a0.z; As[lc + 3][lr] = a0.w;
        As[lc + 16][lr] = a1.x; As[lc + 17][lr] = a1.y;
        As[lc + 18][lr] = a1.z; As[lc + 19][lr] = a1.w;
        Bs[br][bc + 0] = bb.x; Bs[br][bc + 1] = bb.y;
        Bs[br][bc + 2] = bb.z; Bs[br][bc + 3] = bb.w;
        __syncthreads();
#pragma unroll
        for (int kk = 0; kk < 32; kk++) {
            const float4 a = *(const float4*)&As[kk][ty * 4];
            const float2 b = *(const float2*)&Bs[kk][tx * 2];
            const ull a01 = ((const ull*)&a)[0];
            const ull a23 = ((const ull*)&a)[1];
            ull bx2, by2; PK2(bx2, b.x, b.x); PK2(by2, b.y, b.y);
            FFMA2(accp[0][0], a01, bx2, accp[0][0]);
            FFMA2(accp[0][1], a23, bx2, accp[0][1]);
            FFMA2(accp[1][0], a01, by2, accp[1][0]);
            FFMA2(accp[1][1], a23, by2, accp[1][1]);
        }
        __syncthreads();
    }

    const float b0 = (ks == 0) ? bias[c0 + tx * 2]     : 0.f;
    const float b1 = (ks == 0) ? bias[c0 + tx * 2 + 1] : 0.f;
    float c00, c10, c20, c30, c01, c11, c21, c31;
    UPK2(c00, c10, accp[0][0]); UPK2(c20, c30, accp[0][1]);
    UPK2(c01, c11, accp[1][0]); UPK2(c21, c31, accp[1][1]);
    float cj0[4] = {c00, c10, c20, c30};
    float cj1[4] = {c01, c11, c21, c31};
#pragma unroll
    for (int i = 0; i < 4; i++) {
        float2 o = make_float2(cj0[i] + b0, cj1[i] + b1);
        *(float2*)(Y + (size_t)(ty * 4 + i) * DD + c0 + tx * 2) = o;
    }
}

// ---------------------------------------------------------------------------
// Kernel 2: per (n,h) scores, q-split x2 for occupancy.
// grid (64 nh, 6 tasks, 2 q-halves of 32), 256 threads.
//   task<5 : A[nh][e][q-half] = sum_d mem[e,h,d] * Q[n,q,h,d]
//   task=5 : B[nh][k][q-half] = sum_d K[k,h,d]  * Q[n,q,h,d]
// Q and K arrive as 2 k-halves; sum while staging.
// ---------------------------------------------------------------------------
__global__ __launch_bounds__(256) void scores_kernel(
    const float* __restrict__ mem, const float* __restrict__ Q,
    const float* __restrict__ K, float* __restrict__ A, float* __restrict__ B)
{
    const int nh = blockIdx.x;          // 0..63
    const int n = nh >> 4, h = nh & 15;
    const int task = blockIdx.y;        // 0..4 = A e-tiles, 5 = B
    const int q0 = blockIdx.z * 32;     // q half

    __shared__ float Ls[48][68];        // [d][r] (272B rows, float4-safe)
    __shared__ float Qs[48][36];        // [d][q-local] (144B rows, float4-safe)

    const int tid = threadIdx.x;

    // Load Qs: 32 q rows of this half, summing the 2 k-halves.
    // thread (r = tid>>3 in [0,32), c = tid&7): 6 d values at d = c*6..c*6+5
    {
        const int r = tid >> 3;
        const int c = tid & 7;
        const float* srcQ0 = Q + (size_t)(n * QL + q0 + r) * DD + h * HD + c * 6;
        const float* srcQ1 = srcQ0 + (size_t)NN * QL * DD;
#pragma unroll
        for (int j = 0; j < 3; j++) {
            const float2 a = *(const float2*)(srcQ0 + j * 2);
            const float2 b = *(const float2*)(srcQ1 + j * 2);
            const int d = c * 6 + j * 2;
            Qs[d][r]     = a.x + b.x;
            Qs[d + 1][r] = a.y + b.y;
        }
    }
    // Load Ls: full 64 rows (mem e-tile or K with halves summed).
    {
        const int r = tid >> 2;         // 0..63
        const int c = tid & 3;
        if (task < 5) {
            const int R = min(64, EE - task * 64);
            const float* srcL = mem + (size_t)(task * 64 + r) * DD + h * HD;
#pragma unroll
            for (int j = 0; j < 3; j++) {
                const int d0 = c * 4 + j * 16;
                float4 vl = make_float4(0.f, 0.f, 0.f, 0.f);
                if (r < R) vl = *(const float4*)(srcL + d0);
                Ls[d0 + 0][r] = vl.x; Ls[d0 + 1][r] = vl.y;
                Ls[d0 + 2][r] = vl.z; Ls[d0 + 3][r] = vl.w;
            }
        } else {
            const float* srcK0 = K + (size_t)r * DD + h * HD;
            const float* srcK1 = srcK0 + (size_t)KL * DD;
#pragma unroll
            for (int j = 0; j < 3; j++) {
                const int d0 = c * 4 + j * 16;
                const float4 k0v = *(const float4*)(srcK0 + d0);
                const float4 k1v = *(const float4*)(srcK1 + d0);
                Ls[d0 + 0][r] = k0v.x + k1v.x; Ls[d0 + 1][r] = k0v.y + k1v.y;
                Ls[d0 + 2][r] = k0v.z + k1v.z; Ls[d0 + 3][r] = k0v.w + k1v.w;
            }
        }
    }
    __syncthreads();

    // Microtile: thread (tx = tid&7 -> 4 q, ty = tid>>3 -> 2 L-rows)
    const int tx = tid & 7, ty = tid >> 3;
    ull accp[2][2];
    accp[0][0] = accp[0][1] = accp[1][0] = accp[1][1] = 0ull;

#pragma unroll 8
    for (int d = 0; d < 48; d++) {
        const float2 a = *(const float2*)&Ls[d][ty * 2];
        const float4 b = *(const float4*)&Qs[d][tx * 4];
        const ull b01 = ((const ull*)&b)[0];
        const ull b23 = ((const ull*)&b)[1];
        ull ax2, ay2;
        PK2(ax2, a.x, a.x); PK2(ay2, a.y, a.y);
        FFMA2(accp[0][0], b01, ax2, accp[0][0]); FFMA2(accp[0][1], b23, ax2, accp[0][1]);
        FFMA2(accp[1][0], b01, ay2, accp[1][0]); FFMA2(accp[1][1], b23, ay2, accp[1][1]);
    }

    if (task < 5) {
        float* out = A + (size_t)nh * EE * QL + q0;
#pragma unroll
        for (int i = 0; i < 2; i++) {
            int e = task * 64 + ty * 2 + i;
            if (e < EE) {
                float4 o;
                UPK2(o.x, o.y, accp[i][0]); UPK2(o.z, o.w, accp[i][1]);
                *(float4*)(out + (size_t)e * QL + tx * 4) = o;
            }
        }
    } else {
        float* out = B + (size_t)nh * KL * QL + q0;
#pragma unroll
        for (int i = 0; i < 2; i++) {
            float4 o;
            UPK2(o.x, o.y, accp[i][0]); UPK2(o.z, o.w, accp[i][1]);
            *(float4*)(out + (size_t)(ty * 2 + i) * QL + tx * 4) = o;
        }
    }
}

// ---------------------------------------------------------------------------
// Kernel 3 (FUSED tsum+wk, f32x2): one 64-e tile per block. (R10 shape)
//   pass1: Tsh[e][k] = sum_q relu(A[e,q]+B[k,q]) (k local 0..31)
//   pass2: w[k,q] += relu(A[e,q]+B[k,q]) * Tsh[e][k]
// grid (64 nh, 2 k-halves of 32, 5 e-chunks of 64), 256 threads.
// ---------------------------------------------------------------------------
__global__ __launch_bounds__(256) void wkfused_kernel(
    const float* __restrict__ A, const float* __restrict__ B,
    float* __restrict__ Wp)
{
    const int nh = blockIdx.x;
    const int kg = blockIdx.y;          // 0,1
    const int es = blockIdx.z;          // 0..4
    const int e0 = es * 64;
    const int ec = min(64, EE - e0);    // 64,64,64,64,44

    __shared__ float Ash[64][64];       // [e][q] (256B rows, float4-safe)
    __shared__ float Bsh[32][66];       // [k-local][q] (264B rows, ull-safe)
    __shared__ float Tsh[64][32];       // [e][k-local] (128B rows)

    const int tid = threadIdx.x;
    const int qx = tid & 15;            // pass2: q4 = qx*4
    const int ky = tid >> 4;            // pass2: local k pair = ky*2, ky*2+1
    const int kp = tid & 31;            // pass1: local k
    const int eb = tid >> 5;            // pass1: warp -> e group of 8

    const float* Bb = B + ((size_t)nh * KL + kg * 32) * QL;

    // load Bsh (32 x 64)
#pragma unroll
    for (int i = 0; i < 2; i++) {
        int f = tid + i * 256;
        int k = f >> 4, qq = (f & 15) * 4;
        float4 v = *(const float4*)(Bb + (size_t)k * QL + qq);
        Bsh[k][qq + 0] = v.x; Bsh[k][qq + 1] = v.y;
        Bsh[k][qq + 2] = v.z; Bsh[k][qq + 3] = v.w;
    }

    // pass2 per-thread B registers (as packed pairs)
    const float4 b0 = *(const float4*)(Bb + (size_t)(ky * 2) * QL + qx * 4);
    const float4 b1 = *(const float4*)(Bb + (size_t)(ky * 2 + 1) * QL + qx * 4);
    const ull b0a = ((const ull*)&b0)[0], b0b = ((const ull*)&b0)[1];
    const ull b1a = ((const ull*)&b1)[0], b1b = ((const ull*)&b1)[1];

    ull w0a = 0ull, w0b = 0ull, w1a = 0ull, w1b = 0ull;

    const float* Ab = A + (size_t)nh * EE * QL;

    // load A tile: 4 float4/thread (zero-pad beyond ec)
#pragma unroll
    for (int i = 0; i < 4; i++) {
        int f = tid + i * 256;
        int e = f >> 4, qq = (f & 15) * 4;
        float4 v = make_float4(0.f, 0.f, 0.f, 0.f);
        if (e < ec) v = *(const float4*)(Ab + (size_t)(e0 + e) * QL + qq);
        *(float4*)&Ash[e][qq] = v;
    }
    __syncthreads();

    // pass1: each thread sums 8 e rows (e = eb*8 + i) over all 64 q (packed pairs)
    {
        ull tacc2[8];
#pragma unroll
        for (int i = 0; i < 8; i++) tacc2[i] = 0ull;
#pragma unroll 4
        for (int q2 = 0; q2 < 32; q2++) {
            const ull b2 = *(const ull*)&Bsh[kp][q2 * 2];
#pragma unroll
            for (int i = 0; i < 8; i++) {
                const ull a2 = *(const ull*)&Ash[eb * 8 + i][q2 * 2];
                ull p; FADD2(p, a2, b2);
                p = relu2(p);
                FADD2(tacc2[i], tacc2[i], p);
            }
        }
#pragma unroll
        for (int i = 0; i < 8; i++) {
            const int e = eb * 8 + i;
            float x, y; UPK2(x, y, tacc2[i]);
            Tsh[e][kp] = (e < ec) ? (x + y) : 0.f;  // zero padded rows
        }
    }
    __syncthreads();

    // pass2: microtile accumulate (packed)
#pragma unroll 8
    for (int e = 0; e < 64; e++) {
        const float4 a = *(const float4*)&Ash[e][qx * 4];
        const ull a01 = ((const ull*)&a)[0];
        const ull a23 = ((const ull*)&a)[1];
        const float2 t = *(const float2*)&Tsh[e][ky * 2];
        ull tx2, ty2; PK2(tx2, t.x, t.x); PK2(ty2, t.y, t.y);
        ull p;
        FADD2(p, a01, b0a); p = relu2(p); FFMA2(w0a, p, tx2, w0a);
        FADD2(p, a23, b0b); p = relu2(p); FFMA2(w0b, p, tx2, w0b);
        FADD2(p, a01, b1a); p = relu2(p); FFMA2(w1a, p, ty2, w1a);
        FADD2(p, a23, b1b); p = relu2(p); FFMA2(w1b, p, ty2, w1b);
    }

    float4 w0, w1;
    UPK2(w0.x, w0.y, w0a); UPK2(w0.z, w0.w, w0b);
    UPK2(w1.x, w1.y, w1a); UPK2(w1.z, w1.w, w1b);

    float* Wb = Wp + ((size_t)es * NH + nh) * KL * QL + (size_t)kg * 32 * QL;
    *(float4*)(Wb + (size_t)(ky * 2) * QL + qx * 4)     = w0;
    *(float4*)(Wb + (size_t)(ky * 2 + 1) * QL + qx * 4) = w1;
}

// ---------------------------------------------------------------------------
// Kernel 4: out[n,q,h,d] = sum_k (sum_es Wp[es])[nh][k][q] * V[k,h,d]
// grid (64 nh, 4 q-quarters of 16), 256 threads. (R10 shape, measured best)
// ---------------------------------------------------------------------------
__global__ __launch_bounds__(256) void out_kernel(
    const float* __restrict__ Wp, const float* __restrict__ V, float* __restrict__ out)
{
    const int nh = blockIdx.x;
    const int qy = blockIdx.y;          // q quarter
    const int n = nh >> 4, h = nh & 15;
    const int q0 = qy * 16;

    __shared__ float Ws[64][16];   // [k][q-local] (64B rows, float4-safe)
    __shared__ float Vs[64][48];   // [k][d] (192B rows, float4-safe)

    const int tid = threadIdx.x;
    const float* Wb = Wp + (size_t)nh * KL * QL + q0;

    // Ws: 1024 floats = 1 float4/thread, summing ESPLIT partials
    {
        int k = tid >> 2, qq = (tid & 3) * 4;
        const float* p = Wb + (size_t)k * QL + qq;
        float4 s = make_float4(0.f, 0.f, 0.f, 0.f);
#pragma unroll
        for (int es = 0; es < ESPLIT; es++) {
            const float4 v = *(const float4*)(p + (size_t)es * NH * KL * QL);
            s.x += v.x; s.y += v.y; s.z += v.z; s.w += v.w;
        }
        *(float4*)&Ws[k][qq] = s;
    }
    // Vs: 3072 floats = 3 float4/thread, summing 2 k-halves
#pragma unroll
    for (int i = 0; i < 3; i++) {
        int f = tid + i * 256;
        int k = f / 12, d4 = (f % 12) * 4;
        const float* p0 = V + (size_t)k * DD + h * HD + d4;
        const float4 v0 = *(const float4*)p0;
        const float4 v1 = *(const float4*)(p0 + (size_t)KL * DD);
        float4 s = make_float4(v0.x + v1.x, v0.y + v1.y, v0.z + v1.z, v0.w + v1.w);
        *(float4*)&Vs[k][d4] = s;
    }
    __syncthreads();

    const int tx = tid & 15;      // d group of 3
    const int ty = tid >> 4;      // q local (1 each)
    float acc[3] = {0.f, 0.f, 0.f};

#pragma unroll 8
    for (int kk = 0; kk < 64; kk++) {
        const float wq = Ws[kk][ty];
        acc[0] = fmaf(wq, Vs[kk][tx * 3 + 0], acc[0]);
        acc[1] = fmaf(wq, Vs[kk][tx * 3 + 1], acc[1]);
        acc[2] = fmaf(wq, Vs[kk][tx * 3 + 2], acc[2]);
    }

    const int q = q0 + ty;
#pragma unroll
    for (int j = 0; j < 3; j++)
        out[(size_t)(n * QL + q) * DD + h * HD + tx * 3 + j] = acc[j];
}

// ---------------------------------------------------------------------------
// Launch
// Inputs: 0=q 1=k 2=v 3=Wq 4=bq 5=Wk 6=bk 7=Wv 8=bv 9=memory
// ---------------------------------------------------------------------------
extern "C" void kernel_launch(void* const* d_in, const int* in_sizes, int n_in,
                              void* d_out, int out_size)
{
    const float* q   = (const float*)d_in[0];
    const float* k   = (const float*)d_in[1];
    const float* v   = (const float*)d_in[2];
    const float* Wq  = (const float*)d_in[3];
    const float* bq  = (const float*)d_in[4];
    const float* Wk  = (const float*)d_in[5];
    const float* bk  = (const float*)d_in[6];
    const float* Wv  = (const float*)d_in[7];
    const float* bv  = (const float*)d_in[8];
    const float* mem = (const float*)d_in[9];
    float* out = (float*)d_out;

    float *gQ, *gK, *gV, *gA, *gB, *gWp;
    cudaGetSymbolAddress((void**)&gQ, g_Q);
    cudaGetSymbolAddress((void**)&gK, g_K);
    cudaGetSymbolAddress((void**)&gV, g_V);
    cudaGetSymbolAddress((void**)&gA, g_A);
    cudaGetSymbolAddress((void**)&gB, g_B);
    cudaGetSymbolAddress((void**)&gWp, g_Wp);

    // 1. Fused projections, k-split x2 (288 blocks)
    proj_kernel<<<dim3(6, 24, 2), 256>>>(q, k, v, Wq, Wk, Wv, bq, bk, bv, gQ, gK, gV);

    // 2. A (mem·Q) and B (K·Q) scores, q-split x2 (768 blocks)
    scores_kernel<<<dim3(NH, 6, 2), 256>>>(mem, gQ, gK, gA, gB);

    // 3. Fused T+W partials: 2 k-halves x 5 e-chunks (640 blocks, R10 shape)
    wkfused_kernel<<<dim3(NH, 2, ESPLIT), 256>>>(gA, gB, gWp);

    // 4. out = (sum of W partials)^T @ V_h (256 blocks, R10 shape)
    out_kernel<<<dim3(NH, 4), 256>>>(gWp, gV, out);
}